// round 7
// baseline (speedup 1.0000x reference)
#include <cuda_runtime.h>
#include <math.h>
#include <float.h>

// Shapes (fixed): x [8,512,64,64] f32; w1 [32,512]; b1 [32]; w2 [512,32]; b2 [512]
#define NPLANES 4096
#define PLANE_ELEMS 4096
#define HW 64
#define NEG_INF (-FLT_MAX)

// padded tile: 64 rows, stride 80 floats, data cols [8,72)
#define TSTR 80
#define TOFF 8
// row-max arrays: stride 64, 6 pad rows top/bottom; rowB shares its top pad
// band with rowS's bottom pad band (both constant -inf).
#define RSTR 64
#define ROFF 6

#define SM_TILE   (64 * TSTR)                 // 5120 floats
#define ROWS_OFF  SM_TILE
#define ROWB_OFF  (SM_TILE + 70 * RSTR)
#define SMEM_FLOATS (SM_TILE + 70 * RSTR + 76 * RSTR)   // 14464 floats = 57856 B

#define POOL_GRID 444                         // 148 SMs * 3 CTAs
#define CHUNK 1024                            // planes per pool launch

// Scratch (no allocations allowed -> device globals)
__device__ float g_gap[NPLANES];
__device__ int   g_q[NPLANES];
__device__ float g_fb[NPLANES];

// ---------------------------------------------------------------------------
// Kernel 1: per-plane mean
// ---------------------------------------------------------------------------
__global__ __launch_bounds__(256) void gap_kernel(const float* __restrict__ x) {
    const int plane = blockIdx.x;
    const float4* __restrict__ p =
        reinterpret_cast<const float4*>(x + (size_t)plane * PLANE_ELEMS);

    float sum = 0.f;
    #pragma unroll 4
    for (int i = threadIdx.x; i < PLANE_ELEMS / 4; i += 256) {
        float4 v = p[i];
        sum += (v.x + v.y) + (v.z + v.w);
    }
    #pragma unroll
    for (int off = 16; off > 0; off >>= 1)
        sum += __shfl_down_sync(0xffffffffu, sum, off);

    __shared__ float warp_sums[8];
    const int lane = threadIdx.x & 31, wid = threadIdx.x >> 5;
    if (lane == 0) warp_sums[wid] = sum;
    __syncthreads();
    if (threadIdx.x == 0) {
        float t = 0.f;
        #pragma unroll
        for (int i = 0; i < 8; i++) t += warp_sums[i];
        g_gap[plane] = t * (1.0f / (float)PLANE_ELEMS);
    }
}

// ---------------------------------------------------------------------------
// Kernel 2: SE bottleneck + routing
// ---------------------------------------------------------------------------
__global__ __launch_bounds__(512) void se_kernel(const float* __restrict__ w1,
                                                 const float* __restrict__ b1,
                                                 const float* __restrict__ w2,
                                                 const float* __restrict__ b2) {
    __shared__ float sgap[512];
    __shared__ float shmid[32];
    const int b = blockIdx.x;
    const int t = threadIdx.x;

    sgap[t] = g_gap[b * 512 + t];
    __syncthreads();

    if (t < 32) {
        float acc = b1[t];
        const float* wr = w1 + t * 512;
        #pragma unroll 8
        for (int k = 0; k < 512; k++) acc = fmaf(sgap[k], wr[k], acc);
        shmid[t] = fmaxf(acc, 0.f);
    }
    __syncthreads();

    float acc = b2[t];
    const float* wr = w2 + t * 32;
    #pragma unroll
    for (int j = 0; j < 32; j++) acc = fmaf(shmid[j], wr[j], acc);
    const float s = fmaxf(acc, 0.f);

    int q = (int)floorf(s);
    q = min(max(q, 0), 5);
    const int plane = b * 512 + t;
    g_q[plane]  = q;
    g_fb[plane] = s - (float)q;
}

// ---------------------------------------------------------------------------
__device__ __forceinline__ float4 fmax4(float4 a, float4 b) {
    return make_float4(fmaxf(a.x, b.x), fmaxf(a.y, b.y),
                       fmaxf(a.z, b.z), fmaxf(a.w, b.w));
}
__device__ __forceinline__ float4 ld4s(const float* p) {
    return *reinterpret_cast<const float4*>(p);
}

// 4 sliding maxes of window W over float4 rows in smem at stride RSTR floats.
template<int W>
__device__ __forceinline__ void colslide(const float* __restrict__ base,
                                         float4 out[4]) {
    if constexpr (W == 1) {
        #pragma unroll
        for (int j = 0; j < 4; j++) out[j] = ld4s(base + j * RSTR);
    } else if constexpr (W <= 3) {
        float4 a[W + 3];
        #pragma unroll
        for (int k = 0; k < W + 3; k++) a[k] = ld4s(base + k * RSTR);
        #pragma unroll
        for (int j = 0; j < 4; j++) {
            float4 m = a[j];
            #pragma unroll
            for (int u = 1; u < W; u++) m = fmax4(m, a[j + u]);
            out[j] = m;
        }
    } else {
        float4 a0 = ld4s(base), a1 = ld4s(base + RSTR), a2 = ld4s(base + 2 * RSTR);
        float4 core = ld4s(base + 3 * RSTR);
        #pragma unroll
        for (int k = 4; k < W; k++) core = fmax4(core, ld4s(base + k * RSTR));
        float4 aW  = ld4s(base + W * RSTR);
        float4 aW1 = ld4s(base + (W + 1) * RSTR);
        float4 aW2 = ld4s(base + (W + 2) * RSTR);
        out[0] = fmax4(fmax4(core, a0), fmax4(a1, a2));
        out[1] = fmax4(fmax4(core, a1), fmax4(a2, aW));
        out[2] = fmax4(fmax4(core, a2), fmax4(aW, aW1));
        out[3] = fmax4(fmax4(core, aW), fmax4(aW1, aW2));
    }
}

// ---------------------------------------------------------------------------
// Per-plane compute (tile already loaded & synced by caller).
// Residual from GMEM so tile is dead after the row pass.
// ---------------------------------------------------------------------------
template<int R>
__device__ __forceinline__ void process_plane(
    const float* __restrict__ xg, float* __restrict__ outg,
    const float* __restrict__ tile, float* __restrict__ rowS,
    float* __restrict__ rowB, float fb)
{
    const int t = threadIdx.x;
    const float fs = 1.0f - fb;

    // ---- row pass: 4-wide outputs, 5x LDS.128 covers radius R+1 <= 6 ----
    #pragma unroll
    for (int k = 0; k < 4; k++) {
        const int item = t + (k << 8);
        const int y = item >> 4, c = item & 15;
        const float* tb = tile + y * TSTR + (c << 2);   // r[i] = col 4c-8+i
        float r[20];
        #pragma unroll
        for (int u = 0; u < 5; u++)
            *reinterpret_cast<float4*>(&r[4 * u]) = ld4s(tb + 4 * u);

        float mS[4], mB[4];
        if constexpr (R == 0) {
            #pragma unroll
            for (int j = 0; j < 4; j++) mS[j] = r[8 + j];
        } else if constexpr (R == 1) {
            #pragma unroll
            for (int j = 0; j < 4; j++)
                mS[j] = fmaxf(r[7 + j], fmaxf(r[8 + j], r[9 + j]));
        } else {
            float core = r[11 - R];
            #pragma unroll
            for (int u = 12 - R; u <= 8 + R; u++) core = fmaxf(core, r[u]);
            mS[0] = fmaxf(fmaxf(core, r[8 - R]),  fmaxf(r[9 - R],  r[10 - R]));
            mS[1] = fmaxf(fmaxf(core, r[9 - R]),  fmaxf(r[10 - R], r[9 + R]));
            mS[2] = fmaxf(fmaxf(core, r[10 - R]), fmaxf(r[9 + R],  r[10 + R]));
            mS[3] = fmaxf(fmaxf(core, r[9 + R]),  fmaxf(r[10 + R], r[11 + R]));
        }
        #pragma unroll
        for (int j = 0; j < 4; j++)
            mB[j] = fmaxf(mS[j], fmaxf(r[7 - R + j], r[9 + R + j]));

        const int ro = (y + ROFF) * RSTR + (c << 2);
        *reinterpret_cast<float4*>(rowS + ro) = make_float4(mS[0], mS[1], mS[2], mS[3]);
        *reinterpret_cast<float4*>(rowB + ro) = make_float4(mB[0], mB[1], mB[2], mB[3]);
    }
    __syncthreads();   // rowS/rowB ready; tile dead from here

    // ---- column pass: residual from gmem, two register-lean stages ----
    {
        const int c4 = (t & 15) << 2, y0 = (t >> 4) << 2;

        float4 res[4];
        #pragma unroll
        for (int j = 0; j < 4; j++)
            res[j] = *reinterpret_cast<const float4*>(xg + (y0 + j) * HW + c4);

        float4 part[4];
        {
            float4 mS4[4];
            colslide<2 * R + 1>(rowS + (y0 - R + ROFF) * RSTR + c4, mS4);
            #pragma unroll
            for (int j = 0; j < 4; j++) {
                part[j].x = fmaf(fs, mS4[j].x, res[j].x);
                part[j].y = fmaf(fs, mS4[j].y, res[j].y);
                part[j].z = fmaf(fs, mS4[j].z, res[j].z);
                part[j].w = fmaf(fs, mS4[j].w, res[j].w);
            }
        }
        {
            float4 mB4[4];
            colslide<2 * R + 3>(rowB + (y0 - R - 1 + ROFF) * RSTR + c4, mB4);
            #pragma unroll
            for (int j = 0; j < 4; j++) {
                float4 o;
                o.x = fmaf(fb, mB4[j].x, part[j].x);
                o.y = fmaf(fb, mB4[j].y, part[j].y);
                o.z = fmaf(fb, mB4[j].z, part[j].z);
                o.w = fmaf(fb, mB4[j].w, part[j].w);
                *reinterpret_cast<float4*>(outg + (y0 + j) * HW + c4) = o;
            }
        }
    }
    // No trailing sync needed: the next iteration only writes TILE, which
    // col-pass warps never touch; the caller's tile-ready barrier orders
    // everything (a warp can only start the next row pass after ALL warps
    // arrived there, i.e. finished this col pass).
}

// ---------------------------------------------------------------------------
// Kernel 3: processes planes [plane_base, plane_base+CHUNK). 2 barriers/plane.
// Split into 4 launches so ncu's skip-count lands on pool, not gap.
// ---------------------------------------------------------------------------
__global__ __launch_bounds__(256, 3) void pool_kernel(const float* __restrict__ x,
                                                      float* __restrict__ out,
                                                      int plane_base) {
    extern __shared__ float smem[];
    float* tile = smem;
    float* rowS = smem + ROWS_OFF;
    float* rowB = smem + ROWB_OFF;
    const int t = threadIdx.x;

    // fill constant -inf pads once per block
    for (int i = t; i < 64 * 16; i += 256) {
        const int y = i >> 4, c = i & 15;
        const int col = (c < 8) ? c : (64 + c);
        tile[y * TSTR + col] = NEG_INF;
    }
    for (int i = t; i < 18 * 64; i += 256) {
        const int r = i >> 6, cc = i & 63;
        float* p;
        if (r < 6)       p = rowS + r * RSTR + cc;
        else if (r < 12) p = rowB + (r - 6) * RSTR + cc;   // shared band
        else             p = rowB + (70 + r - 12) * RSTR + cc;
        *p = NEG_INF;
    }

    const int plane_end = plane_base + CHUNK;
    int   r  = g_q[plane_base + blockIdx.x];
    float fb = g_fb[plane_base + blockIdx.x];

    for (int plane = plane_base + blockIdx.x; plane < plane_end;
         plane += gridDim.x) {
        const size_t base = (size_t)plane * PLANE_ELEMS;
        const float* xg = x + base;
        float* outg = out + base;

        // load tile
        {
            const float4* __restrict__ src = reinterpret_cast<const float4*>(xg);
            #pragma unroll
            for (int k = 0; k < 4; k++) {
                const int i = t + (k << 8);
                const int y = i >> 4, x4 = (i & 15) << 2;
                *reinterpret_cast<float4*>(tile + y * TSTR + TOFF + x4) = src[i];
            }
        }
        // scalar prefetch of next plane's routing (hides L2 latency)
        int rn = r; float fbn = fb;
        {
            const int pn = plane + gridDim.x;
            if (pn < plane_end) { rn = g_q[pn]; fbn = g_fb[pn]; }
        }
        __syncthreads();   // tile ready (orders pad fill on first iter too)

        switch (r) {
            case 0: process_plane<0>(xg, outg, tile, rowS, rowB, fb); break;
            case 1: process_plane<1>(xg, outg, tile, rowS, rowB, fb); break;
            case 2: process_plane<2>(xg, outg, tile, rowS, rowB, fb); break;
            case 3: process_plane<3>(xg, outg, tile, rowS, rowB, fb); break;
            case 4: process_plane<4>(xg, outg, tile, rowS, rowB, fb); break;
            default: process_plane<5>(xg, outg, tile, rowS, rowB, fb); break;
        }
        r = rn; fb = fbn;
    }
}

// ---------------------------------------------------------------------------
extern "C" void kernel_launch(void* const* d_in, const int* in_sizes, int n_in,
                              void* d_out, int out_size) {
    const float* x  = (const float*)d_in[0];
    const float* w1 = (const float*)d_in[1];
    const float* b1 = (const float*)d_in[2];
    const float* w2 = (const float*)d_in[3];
    const float* b2 = (const float*)d_in[4];
    float* out = (float*)d_out;

    const int smem_bytes = SMEM_FLOATS * (int)sizeof(float);   // 57856
    cudaFuncSetAttribute(pool_kernel,
                         cudaFuncAttributeMaxDynamicSharedMemorySize, smem_bytes);

    gap_kernel<<<NPLANES, 256>>>(x);
    se_kernel<<<8, 512>>>(w1, b1, w2, b2);
    pool_kernel<<<POOL_GRID, 256, smem_bytes>>>(x, out, 0);
    pool_kernel<<<POOL_GRID, 256, smem_bytes>>>(x, out, 1024);
    pool_kernel<<<POOL_GRID, 256, smem_bytes>>>(x, out, 2048);
    pool_kernel<<<POOL_GRID, 256, smem_bytes>>>(x, out, 3072);
}

// round 8
// speedup vs baseline: 1.0217x; 1.0217x over previous
#include <cuda_runtime.h>
#include <math.h>
#include <float.h>

// Shapes (fixed): x [8,512,64,64] f32; w1 [32,512]; b1 [32]; w2 [512,32]; b2 [512]
#define NPLANES 4096
#define PLANE_ELEMS 4096
#define HW 64
#define NEG_INF (-FLT_MAX)

// row-max arrays in smem: stride 64, 6 pad rows top/bottom; rowB's top pad
// band is rowS's bottom pad band (both constant -inf). No tile anymore.
#define RSTR 64
#define ROFF 6
#define ROWS_OFF  0
#define ROWB_OFF  (70 * RSTR)
#define SMEM_FLOATS (70 * RSTR + 76 * RSTR)   // 9344 floats = 37376 B

#define POOL_GRID 592                          // 148 SMs * 4 CTAs
#define CHUNK 1024                             // planes per pool launch

// Scratch (no allocations allowed -> device globals)
__device__ float g_gap[NPLANES];
__device__ int   g_q[NPLANES];
__device__ float g_fb[NPLANES];

// ---------------------------------------------------------------------------
// Kernel 1: per-plane mean
// ---------------------------------------------------------------------------
__global__ __launch_bounds__(256) void gap_kernel(const float* __restrict__ x) {
    const int plane = blockIdx.x;
    const float4* __restrict__ p =
        reinterpret_cast<const float4*>(x + (size_t)plane * PLANE_ELEMS);

    float sum = 0.f;
    #pragma unroll 4
    for (int i = threadIdx.x; i < PLANE_ELEMS / 4; i += 256) {
        float4 v = p[i];
        sum += (v.x + v.y) + (v.z + v.w);
    }
    #pragma unroll
    for (int off = 16; off > 0; off >>= 1)
        sum += __shfl_down_sync(0xffffffffu, sum, off);

    __shared__ float warp_sums[8];
    const int lane = threadIdx.x & 31, wid = threadIdx.x >> 5;
    if (lane == 0) warp_sums[wid] = sum;
    __syncthreads();
    if (threadIdx.x == 0) {
        float t = 0.f;
        #pragma unroll
        for (int i = 0; i < 8; i++) t += warp_sums[i];
        g_gap[plane] = t * (1.0f / (float)PLANE_ELEMS);
    }
}

// ---------------------------------------------------------------------------
// Kernel 2: SE bottleneck + routing
// ---------------------------------------------------------------------------
__global__ __launch_bounds__(512) void se_kernel(const float* __restrict__ w1,
                                                 const float* __restrict__ b1,
                                                 const float* __restrict__ w2,
                                                 const float* __restrict__ b2) {
    __shared__ float sgap[512];
    __shared__ float shmid[32];
    const int b = blockIdx.x;
    const int t = threadIdx.x;

    sgap[t] = g_gap[b * 512 + t];
    __syncthreads();

    if (t < 32) {
        float acc = b1[t];
        const float* wr = w1 + t * 512;
        #pragma unroll 8
        for (int k = 0; k < 512; k++) acc = fmaf(sgap[k], wr[k], acc);
        shmid[t] = fmaxf(acc, 0.f);
    }
    __syncthreads();

    float acc = b2[t];
    const float* wr = w2 + t * 32;
    #pragma unroll
    for (int j = 0; j < 32; j++) acc = fmaf(shmid[j], wr[j], acc);
    const float s = fmaxf(acc, 0.f);

    int q = (int)floorf(s);
    q = min(max(q, 0), 5);
    const int plane = b * 512 + t;
    g_q[plane]  = q;
    g_fb[plane] = s - (float)q;
}

// ---------------------------------------------------------------------------
__device__ __forceinline__ float4 fmax4(float4 a, float4 b) {
    return make_float4(fmaxf(a.x, b.x), fmaxf(a.y, b.y),
                       fmaxf(a.z, b.z), fmaxf(a.w, b.w));
}
__device__ __forceinline__ float4 ld4s(const float* p) {
    return *reinterpret_cast<const float4*>(p);
}

// 4 sliding maxes of window W over float4 rows in smem at stride RSTR floats.
// Streaming: head(3) + running core + tail(3) live.
template<int W>
__device__ __forceinline__ void colslide(const float* __restrict__ base,
                                         float4 out[4]) {
    if constexpr (W == 1) {
        #pragma unroll
        for (int j = 0; j < 4; j++) out[j] = ld4s(base + j * RSTR);
    } else if constexpr (W <= 3) {
        float4 a[W + 3];
        #pragma unroll
        for (int k = 0; k < W + 3; k++) a[k] = ld4s(base + k * RSTR);
        #pragma unroll
        for (int j = 0; j < 4; j++) {
            float4 m = a[j];
            #pragma unroll
            for (int u = 1; u < W; u++) m = fmax4(m, a[j + u]);
            out[j] = m;
        }
    } else {
        float4 a0 = ld4s(base), a1 = ld4s(base + RSTR), a2 = ld4s(base + 2 * RSTR);
        float4 core = ld4s(base + 3 * RSTR);
        #pragma unroll
        for (int k = 4; k < W; k++) core = fmax4(core, ld4s(base + k * RSTR));
        float4 aW  = ld4s(base + W * RSTR);
        float4 aW1 = ld4s(base + (W + 1) * RSTR);
        float4 aW2 = ld4s(base + (W + 2) * RSTR);
        out[0] = fmax4(fmax4(core, a0), fmax4(a1, a2));
        out[1] = fmax4(fmax4(core, a1), fmax4(a2, aW));
        out[2] = fmax4(fmax4(core, a2), fmax4(aW, aW1));
        out[3] = fmax4(fmax4(core, aW), fmax4(aW1, aW2));
    }
}

// ---------------------------------------------------------------------------
// Per-plane compute, NO tile: row pass reads gmem quads + warp shuffles for
// neighbor columns (needs cols 4c-6 .. 4c+9, i.e. lanes +-2, since R+1 <= 6).
// Lane layout: lanes 0-15 = row y, lanes 16-31 = row y+1; masks at c==0/15.
// ---------------------------------------------------------------------------
template<int R>
__device__ __forceinline__ void process_plane(
    const float* __restrict__ xg, float* __restrict__ outg,
    float* __restrict__ rowS, float* __restrict__ rowB, float fb)
{
    const int t = threadIdx.x;
    const int c = t & 15;                       // col-quad within row
    const float fs = 1.0f - fb;
    const unsigned FULL = 0xffffffffu;

    // ---- row pass ----
    #pragma unroll
    for (int k = 0; k < 4; k++) {
        const int i = t + (k << 8);             // quad index; i&15 == c
        const int y = i >> 4;
        const float4 q = *reinterpret_cast<const float4*>(xg + (i << 2));

        // r[idx] = value at logical col 4c - 8 + idx; only r[2..17] used (R<=5)
        float r[20];
        r[8] = q.x; r[9] = q.y; r[10] = q.z; r[11] = q.w;
        r[4]  = __shfl_up_sync(FULL, q.x, 1);
        r[5]  = __shfl_up_sync(FULL, q.y, 1);
        r[6]  = __shfl_up_sync(FULL, q.z, 1);
        r[7]  = __shfl_up_sync(FULL, q.w, 1);
        r[2]  = __shfl_up_sync(FULL, q.z, 2);
        r[3]  = __shfl_up_sync(FULL, q.w, 2);
        r[12] = __shfl_down_sync(FULL, q.x, 1);
        r[13] = __shfl_down_sync(FULL, q.y, 1);
        r[14] = __shfl_down_sync(FULL, q.z, 1);
        r[15] = __shfl_down_sync(FULL, q.w, 1);
        r[16] = __shfl_down_sync(FULL, q.x, 2);
        r[17] = __shfl_down_sync(FULL, q.y, 2);
        if (c < 1)  { r[4] = r[5] = r[6] = r[7] = NEG_INF; }
        if (c < 2)  { r[2] = r[3] = NEG_INF; }
        if (c > 14) { r[12] = r[13] = r[14] = r[15] = NEG_INF; }
        if (c > 13) { r[16] = r[17] = NEG_INF; }

        float mS[4], mB[4];
        if constexpr (R == 0) {
            #pragma unroll
            for (int j = 0; j < 4; j++) mS[j] = r[8 + j];
        } else if constexpr (R == 1) {
            #pragma unroll
            for (int j = 0; j < 4; j++)
                mS[j] = fmaxf(r[7 + j], fmaxf(r[8 + j], r[9 + j]));
        } else {
            float core = r[11 - R];
            #pragma unroll
            for (int u = 12 - R; u <= 8 + R; u++) core = fmaxf(core, r[u]);
            mS[0] = fmaxf(fmaxf(core, r[8 - R]),  fmaxf(r[9 - R],  r[10 - R]));
            mS[1] = fmaxf(fmaxf(core, r[9 - R]),  fmaxf(r[10 - R], r[9 + R]));
            mS[2] = fmaxf(fmaxf(core, r[10 - R]), fmaxf(r[9 + R],  r[10 + R]));
            mS[3] = fmaxf(fmaxf(core, r[9 + R]),  fmaxf(r[10 + R], r[11 + R]));
        }
        #pragma unroll
        for (int j = 0; j < 4; j++)
            mB[j] = fmaxf(mS[j], fmaxf(r[7 - R + j], r[9 + R + j]));

        const int ro = (y + ROFF) * RSTR + (c << 2);
        *reinterpret_cast<float4*>(rowS + ro) = make_float4(mS[0], mS[1], mS[2], mS[3]);
        *reinterpret_cast<float4*>(rowB + ro) = make_float4(mB[0], mB[1], mB[2], mB[3]);
    }
    __syncthreads();   // rowS/rowB ready

    // ---- column pass: two streaming stages, residual folded between them ----
    {
        const int c4 = c << 2, y0 = (t >> 4) << 2;
        float4 part[4];
        {
            float4 mS4[4];
            colslide<2 * R + 1>(rowS + (y0 - R + ROFF) * RSTR + c4, mS4);
            #pragma unroll
            for (int j = 0; j < 4; j++) {
                part[j].x = fs * mS4[j].x;
                part[j].y = fs * mS4[j].y;
                part[j].z = fs * mS4[j].z;
                part[j].w = fs * mS4[j].w;
            }
        }
        #pragma unroll
        for (int j = 0; j < 4; j++) {
            const float4 res =
                *reinterpret_cast<const float4*>(xg + (y0 + j) * HW + c4);
            part[j].x += res.x; part[j].y += res.y;
            part[j].z += res.z; part[j].w += res.w;
        }
        {
            float4 mB4[4];
            colslide<2 * R + 3>(rowB + (y0 - R - 1 + ROFF) * RSTR + c4, mB4);
            #pragma unroll
            for (int j = 0; j < 4; j++) {
                float4 o;
                o.x = fmaf(fb, mB4[j].x, part[j].x);
                o.y = fmaf(fb, mB4[j].y, part[j].y);
                o.z = fmaf(fb, mB4[j].z, part[j].z);
                o.w = fmaf(fb, mB4[j].w, part[j].w);
                *reinterpret_cast<float4*>(outg + (y0 + j) * HW + c4) = o;
            }
        }
    }
    // No trailing sync: next plane's row pass only writes rowS/rowB AFTER the
    // caller's per-plane barrier below.
}

// ---------------------------------------------------------------------------
// Kernel 3: processes planes [plane_base, plane_base+CHUNK)
// ---------------------------------------------------------------------------
__global__ __launch_bounds__(256, 4) void pool_kernel(const float* __restrict__ x,
                                                      float* __restrict__ out,
                                                      int plane_base) {
    extern __shared__ float smem[];
    float* rowS = smem + ROWS_OFF;
    float* rowB = smem + ROWB_OFF;
    const int t = threadIdx.x;

    // fill constant -inf pads once per block:
    // rowS rows 0..5, shared band (rowS 70..75 == rowB 0..5), rowB rows 70..75
    for (int i = t; i < 18 * 64; i += 256) {
        const int r = i >> 6, cc = i & 63;
        float* p;
        if (r < 6)       p = rowS + r * RSTR + cc;
        else if (r < 12) p = rowB + (r - 6) * RSTR + cc;
        else             p = rowB + (70 + r - 12) * RSTR + cc;
        *p = NEG_INF;
    }
    __syncthreads();   // pads visible before first col pass

    const int plane_end = plane_base + CHUNK;
    int   r  = g_q[plane_base + blockIdx.x];
    float fb = g_fb[plane_base + blockIdx.x];

    for (int plane = plane_base + blockIdx.x; plane < plane_end;
         plane += gridDim.x) {
        const size_t base = (size_t)plane * PLANE_ELEMS;
        const float* xg = x + base;
        float* outg = out + base;

        // prefetch next plane's routing scalars
        int rn = r; float fbn = fb;
        {
            const int pn = plane + gridDim.x;
            if (pn < plane_end) { rn = g_q[pn]; fbn = g_fb[pn]; }
        }

        switch (r) {
            case 0: process_plane<0>(xg, outg, rowS, rowB, fb); break;
            case 1: process_plane<1>(xg, outg, rowS, rowB, fb); break;
            case 2: process_plane<2>(xg, outg, rowS, rowB, fb); break;
            case 3: process_plane<3>(xg, outg, rowS, rowB, fb); break;
            case 4: process_plane<4>(xg, outg, rowS, rowB, fb); break;
            default: process_plane<5>(xg, outg, rowS, rowB, fb); break;
        }
        __syncthreads();   // col pass done before next row pass writes smem
        r = rn; fb = fbn;
    }
}

// ---------------------------------------------------------------------------
extern "C" void kernel_launch(void* const* d_in, const int* in_sizes, int n_in,
                              void* d_out, int out_size) {
    const float* x  = (const float*)d_in[0];
    const float* w1 = (const float*)d_in[1];
    const float* b1 = (const float*)d_in[2];
    const float* w2 = (const float*)d_in[3];
    const float* b2 = (const float*)d_in[4];
    float* out = (float*)d_out;

    const int smem_bytes = SMEM_FLOATS * (int)sizeof(float);   // 37376
    cudaFuncSetAttribute(pool_kernel,
                         cudaFuncAttributeMaxDynamicSharedMemorySize, smem_bytes);

    gap_kernel<<<NPLANES, 256>>>(x);
    se_kernel<<<8, 512>>>(w1, b1, w2, b2);
    pool_kernel<<<POOL_GRID, 256, smem_bytes>>>(x, out, 0);
    pool_kernel<<<POOL_GRID, 256, smem_bytes>>>(x, out, 1024);
    pool_kernel<<<POOL_GRID, 256, smem_bytes>>>(x, out, 2048);
    pool_kernel<<<POOL_GRID, 256, smem_bytes>>>(x, out, 3072);
}

// round 9
// speedup vs baseline: 1.1578x; 1.1333x over previous
#include <cuda_runtime.h>
#include <math.h>
#include <float.h>

// Shapes (fixed): x [8,512,64,64] f32; w1 [32,512]; b1 [32]; w2 [512,32]; b2 [512]
#define NPLANES 4096
#define PLANE_ELEMS 4096
#define HW 64
#define NEG_INF (-FLT_MAX)

// row-max arrays in smem: stride 64, 6 pad rows top/bottom; rowB's top pad
// band is rowS's bottom pad band (both constant -inf).
#define RSTR 64
#define ROFF 6
#define ROWS_OFF  0
#define ROWB_OFF  (70 * RSTR)
#define SMEM_FLOATS (70 * RSTR + 76 * RSTR)   // 9344 floats = 37376 B

#define POOL_GRID 592                          // 148 SMs * 4 CTAs

// Scratch (no allocations allowed -> device globals)
__device__ float g_gap[NPLANES];
__device__ int   g_q[NPLANES];
__device__ float g_fb[NPLANES];

// ---------------------------------------------------------------------------
// Kernel 1: per-plane mean
// ---------------------------------------------------------------------------
__global__ __launch_bounds__(256) void gap_kernel(const float* __restrict__ x) {
    const int plane = blockIdx.x;
    const float4* __restrict__ p =
        reinterpret_cast<const float4*>(x + (size_t)plane * PLANE_ELEMS);

    float sum = 0.f;
    #pragma unroll 4
    for (int i = threadIdx.x; i < PLANE_ELEMS / 4; i += 256) {
        float4 v = p[i];
        sum += (v.x + v.y) + (v.z + v.w);
    }
    #pragma unroll
    for (int off = 16; off > 0; off >>= 1)
        sum += __shfl_down_sync(0xffffffffu, sum, off);

    __shared__ float warp_sums[8];
    const int lane = threadIdx.x & 31, wid = threadIdx.x >> 5;
    if (lane == 0) warp_sums[wid] = sum;
    __syncthreads();
    if (threadIdx.x == 0) {
        float t = 0.f;
        #pragma unroll
        for (int i = 0; i < 8; i++) t += warp_sums[i];
        g_gap[plane] = t * (1.0f / (float)PLANE_ELEMS);
    }
}

// ---------------------------------------------------------------------------
// Kernel 2: SE bottleneck + routing
// ---------------------------------------------------------------------------
__global__ __launch_bounds__(512) void se_kernel(const float* __restrict__ w1,
                                                 const float* __restrict__ b1,
                                                 const float* __restrict__ w2,
                                                 const float* __restrict__ b2) {
    __shared__ float sgap[512];
    __shared__ float shmid[32];
    const int b = blockIdx.x;
    const int t = threadIdx.x;

    sgap[t] = g_gap[b * 512 + t];
    __syncthreads();

    if (t < 32) {
        float acc = b1[t];
        const float* wr = w1 + t * 512;
        #pragma unroll 8
        for (int k = 0; k < 512; k++) acc = fmaf(sgap[k], wr[k], acc);
        shmid[t] = fmaxf(acc, 0.f);
    }
    __syncthreads();

    float acc = b2[t];
    const float* wr = w2 + t * 32;
    #pragma unroll
    for (int j = 0; j < 32; j++) acc = fmaf(shmid[j], wr[j], acc);
    const float s = fmaxf(acc, 0.f);

    int q = (int)floorf(s);
    q = min(max(q, 0), 5);
    const int plane = b * 512 + t;
    g_q[plane]  = q;
    g_fb[plane] = s - (float)q;
}

// ---------------------------------------------------------------------------
__device__ __forceinline__ float4 fmax4(float4 a, float4 b) {
    return make_float4(fmaxf(a.x, b.x), fmaxf(a.y, b.y),
                       fmaxf(a.z, b.z), fmaxf(a.w, b.w));
}
__device__ __forceinline__ float4 ld4s(const float* p) {
    return *reinterpret_cast<const float4*>(p);
}

// 4 sliding maxes of window W over float4 rows in smem at stride RSTR floats.
template<int W>
__device__ __forceinline__ void colslide(const float* __restrict__ base,
                                         float4 out[4]) {
    if constexpr (W == 1) {
        #pragma unroll
        for (int j = 0; j < 4; j++) out[j] = ld4s(base + j * RSTR);
    } else if constexpr (W <= 3) {
        float4 a[W + 3];
        #pragma unroll
        for (int k = 0; k < W + 3; k++) a[k] = ld4s(base + k * RSTR);
        #pragma unroll
        for (int j = 0; j < 4; j++) {
            float4 m = a[j];
            #pragma unroll
            for (int u = 1; u < W; u++) m = fmax4(m, a[j + u]);
            out[j] = m;
        }
    } else {
        float4 a0 = ld4s(base), a1 = ld4s(base + RSTR), a2 = ld4s(base + 2 * RSTR);
        float4 core = ld4s(base + 3 * RSTR);
        #pragma unroll
        for (int k = 4; k < W; k++) core = fmax4(core, ld4s(base + k * RSTR));
        float4 aW  = ld4s(base + W * RSTR);
        float4 aW1 = ld4s(base + (W + 1) * RSTR);
        float4 aW2 = ld4s(base + (W + 2) * RSTR);
        out[0] = fmax4(fmax4(core, a0), fmax4(a1, a2));
        out[1] = fmax4(fmax4(core, a1), fmax4(a2, aW));
        out[2] = fmax4(fmax4(core, a2), fmax4(aW, aW1));
        out[3] = fmax4(fmax4(core, aW), fmax4(aW1, aW2));
    }
}

// ---------------------------------------------------------------------------
// Per-plane compute. Row pass: gmem quads (all 4 LDGs batched up front for
// MLP) + warp shuffles for neighbor columns. Residual LDGs issued before the
// barrier so their latency hides under the barrier wait.
// Lane layout: lanes 0-15 = one row, lanes 16-31 = next row; c = lane & 15.
// ---------------------------------------------------------------------------
template<int R>
__device__ __forceinline__ void process_plane(
    const float* __restrict__ xg, float* __restrict__ outg,
    float* __restrict__ rowS, float* __restrict__ rowB, float fb)
{
    const int t = threadIdx.x;
    const int c = t & 15;
    const float fs = 1.0f - fb;
    const unsigned FULL = 0xffffffffu;

    // ---- batch all 4 row-pass loads (independent; one exposed round trip) --
    float4 q[4];
    #pragma unroll
    for (int k = 0; k < 4; k++)
        q[k] = *reinterpret_cast<const float4*>(xg + ((t + (k << 8)) << 2));

    // ---- row pass ----
    #pragma unroll
    for (int k = 0; k < 4; k++) {
        const int i = t + (k << 8);
        const int y = i >> 4;

        // r[idx] = value at logical col 4c - 8 + idx; only r[2..17] used
        float r[20];
        r[8] = q[k].x; r[9] = q[k].y; r[10] = q[k].z; r[11] = q[k].w;
        r[4]  = __shfl_up_sync(FULL, q[k].x, 1);
        r[5]  = __shfl_up_sync(FULL, q[k].y, 1);
        r[6]  = __shfl_up_sync(FULL, q[k].z, 1);
        r[7]  = __shfl_up_sync(FULL, q[k].w, 1);
        r[2]  = __shfl_up_sync(FULL, q[k].z, 2);
        r[3]  = __shfl_up_sync(FULL, q[k].w, 2);
        r[12] = __shfl_down_sync(FULL, q[k].x, 1);
        r[13] = __shfl_down_sync(FULL, q[k].y, 1);
        r[14] = __shfl_down_sync(FULL, q[k].z, 1);
        r[15] = __shfl_down_sync(FULL, q[k].w, 1);
        r[16] = __shfl_down_sync(FULL, q[k].x, 2);
        r[17] = __shfl_down_sync(FULL, q[k].y, 2);
        if (c < 1)  { r[4] = r[5] = r[6] = r[7] = NEG_INF; }
        if (c < 2)  { r[2] = r[3] = NEG_INF; }
        if (c > 14) { r[12] = r[13] = r[14] = r[15] = NEG_INF; }
        if (c > 13) { r[16] = r[17] = NEG_INF; }

        float mS[4], mB[4];
        if constexpr (R == 0) {
            #pragma unroll
            for (int j = 0; j < 4; j++) mS[j] = r[8 + j];
        } else if constexpr (R == 1) {
            #pragma unroll
            for (int j = 0; j < 4; j++)
                mS[j] = fmaxf(r[7 + j], fmaxf(r[8 + j], r[9 + j]));
        } else {
            float core = r[11 - R];
            #pragma unroll
            for (int u = 12 - R; u <= 8 + R; u++) core = fmaxf(core, r[u]);
            mS[0] = fmaxf(fmaxf(core, r[8 - R]),  fmaxf(r[9 - R],  r[10 - R]));
            mS[1] = fmaxf(fmaxf(core, r[9 - R]),  fmaxf(r[10 - R], r[9 + R]));
            mS[2] = fmaxf(fmaxf(core, r[10 - R]), fmaxf(r[9 + R],  r[10 + R]));
            mS[3] = fmaxf(fmaxf(core, r[9 + R]),  fmaxf(r[10 + R], r[11 + R]));
        }
        #pragma unroll
        for (int j = 0; j < 4; j++)
            mB[j] = fmaxf(mS[j], fmaxf(r[7 - R + j], r[9 + R + j]));

        const int ro = (y + ROFF) * RSTR + (c << 2);
        *reinterpret_cast<float4*>(rowS + ro) = make_float4(mS[0], mS[1], mS[2], mS[3]);
        *reinterpret_cast<float4*>(rowB + ro) = make_float4(mB[0], mB[1], mB[2], mB[3]);
    }

    // ---- issue residual loads NOW: latency hides under the barrier ----
    const int c4 = c << 2, y0 = (t >> 4) << 2;
    float4 res[4];
    #pragma unroll
    for (int j = 0; j < 4; j++)
        res[j] = *reinterpret_cast<const float4*>(xg + (y0 + j) * HW + c4);

    __syncthreads();   // rowS/rowB ready

    // ---- column pass: two streaming stages ----
    {
        float4 part[4];
        {
            float4 mS4[4];
            colslide<2 * R + 1>(rowS + (y0 - R + ROFF) * RSTR + c4, mS4);
            #pragma unroll
            for (int j = 0; j < 4; j++) {
                part[j].x = fmaf(fs, mS4[j].x, res[j].x);
                part[j].y = fmaf(fs, mS4[j].y, res[j].y);
                part[j].z = fmaf(fs, mS4[j].z, res[j].z);
                part[j].w = fmaf(fs, mS4[j].w, res[j].w);
            }
        }
        {
            float4 mB4[4];
            colslide<2 * R + 3>(rowB + (y0 - R - 1 + ROFF) * RSTR + c4, mB4);
            #pragma unroll
            for (int j = 0; j < 4; j++) {
                float4 o;
                o.x = fmaf(fb, mB4[j].x, part[j].x);
                o.y = fmaf(fb, mB4[j].y, part[j].y);
                o.z = fmaf(fb, mB4[j].z, part[j].z);
                o.w = fmaf(fb, mB4[j].w, part[j].w);
                *reinterpret_cast<float4*>(outg + (y0 + j) * HW + c4) = o;
            }
        }
    }
}

// ---------------------------------------------------------------------------
// Kernel 3: single persistent launch, grid-stride over all planes
// ---------------------------------------------------------------------------
__global__ __launch_bounds__(256, 4) void pool_kernel(const float* __restrict__ x,
                                                      float* __restrict__ out) {
    extern __shared__ float smem[];
    float* rowS = smem + ROWS_OFF;
    float* rowB = smem + ROWB_OFF;
    const int t = threadIdx.x;

    // fill constant -inf pads once per block
    for (int i = t; i < 18 * 64; i += 256) {
        const int r = i >> 6, cc = i & 63;
        float* p;
        if (r < 6)       p = rowS + r * RSTR + cc;
        else if (r < 12) p = rowB + (r - 6) * RSTR + cc;   // shared band
        else             p = rowB + (70 + r - 12) * RSTR + cc;
        *p = NEG_INF;
    }
    __syncthreads();

    int   r  = g_q[blockIdx.x];
    float fb = g_fb[blockIdx.x];

    for (int plane = blockIdx.x; plane < NPLANES; plane += gridDim.x) {
        const size_t base = (size_t)plane * PLANE_ELEMS;
        const float* xg = x + base;
        float* outg = out + base;

        // prefetch next plane's routing scalars
        int rn = r; float fbn = fb;
        {
            const int pn = plane + gridDim.x;
            if (pn < NPLANES) { rn = g_q[pn]; fbn = g_fb[pn]; }
        }

        switch (r) {
            case 0: process_plane<0>(xg, outg, rowS, rowB, fb); break;
            case 1: process_plane<1>(xg, outg, rowS, rowB, fb); break;
            case 2: process_plane<2>(xg, outg, rowS, rowB, fb); break;
            case 3: process_plane<3>(xg, outg, rowS, rowB, fb); break;
            case 4: process_plane<4>(xg, outg, rowS, rowB, fb); break;
            default: process_plane<5>(xg, outg, rowS, rowB, fb); break;
        }
        __syncthreads();   // col pass done before next row pass writes smem
        r = rn; fb = fbn;
    }
}

// ---------------------------------------------------------------------------
extern "C" void kernel_launch(void* const* d_in, const int* in_sizes, int n_in,
                              void* d_out, int out_size) {
    const float* x  = (const float*)d_in[0];
    const float* w1 = (const float*)d_in[1];
    const float* b1 = (const float*)d_in[2];
    const float* w2 = (const float*)d_in[3];
    const float* b2 = (const float*)d_in[4];
    float* out = (float*)d_out;

    const int smem_bytes = SMEM_FLOATS * (int)sizeof(float);   // 37376
    cudaFuncSetAttribute(pool_kernel,
                         cudaFuncAttributeMaxDynamicSharedMemorySize, smem_bytes);

    gap_kernel<<<NPLANES, 256>>>(x);
    se_kernel<<<8, 512>>>(w1, b1, w2, b2);
    pool_kernel<<<POOL_GRID, 256, smem_bytes>>>(x, out);
}